// round 16
// baseline (speedup 1.0000x reference)
#include <cuda_runtime.h>
#include <cuda_fp16.h>
#include <math.h>
#include <stdint.h>

#define T_SEQ   2048
#define D_MODEL 4096
#define NHEADS  32
#define KVHEADS 8
#define HDIM    128
#define WINDOW  1024
#define NPROJ   6144   // 4096 Q + 1024 K + 1024 V

// ---------------- scratch (device globals) ----------------
__device__ __half g_Ah[T_SEQ * D_MODEL];          // A plane: X, later Enc
__device__ __half g_Bp[D_MODEL * NPROJ];          // packed QKV proj weights (D, 6144)
__device__ __half g_Bo[D_MODEL * D_MODEL];        // out proj (N*H, D)
__device__ float  g_QKV[T_SEQ * NPROJ];
// attention operands (single fp16 planes)
__device__ __half g_Qs[T_SEQ * NHEADS * HDIM];
__device__ __half g_Ks[T_SEQ * KVHEADS * HDIM];
__device__ __half g_Vs[T_SEQ * KVHEADS * HDIM];

// ---------------- helpers ----------------
__device__ __forceinline__ void cp16(void* dst, const void* src) {
    uint32_t d = (uint32_t)__cvta_generic_to_shared(dst);
    asm volatile("cp.async.cg.shared.global [%0], [%1], 16;\n" :: "r"(d), "l"(src));
}
__device__ __forceinline__ void cp_commit() { asm volatile("cp.async.commit_group;\n"); }

__device__ __forceinline__ void ldsm4(uint32_t& r0, uint32_t& r1, uint32_t& r2, uint32_t& r3,
                                      const __half* p) {
    uint32_t a = (uint32_t)__cvta_generic_to_shared(p);
    asm volatile("ldmatrix.sync.aligned.m8n8.x4.shared.b16 {%0,%1,%2,%3}, [%4];"
                 : "=r"(r0), "=r"(r1), "=r"(r2), "=r"(r3) : "r"(a));
}
__device__ __forceinline__ void ldsm4t(uint32_t& r0, uint32_t& r1, uint32_t& r2, uint32_t& r3,
                                       const __half* p) {
    uint32_t a = (uint32_t)__cvta_generic_to_shared(p);
    asm volatile("ldmatrix.sync.aligned.m8n8.x4.trans.shared.b16 {%0,%1,%2,%3}, [%4];"
                 : "=r"(r0), "=r"(r1), "=r"(r2), "=r"(r3) : "r"(a));
}
__device__ __forceinline__ void mma16816(float* c, const uint32_t* a, uint32_t b0, uint32_t b1) {
    asm volatile(
        "mma.sync.aligned.m16n8k16.row.col.f32.f16.f16.f32 "
        "{%0,%1,%2,%3}, {%4,%5,%6,%7}, {%8,%9}, {%0,%1,%2,%3};"
        : "+f"(c[0]), "+f"(c[1]), "+f"(c[2]), "+f"(c[3])
        : "r"(a[0]), "r"(a[1]), "r"(a[2]), "r"(a[3]), "r"(b0), "r"(b1));
}
// single-instruction pack: lower half = a, upper half = b (matches __halves2half2(a,b))
__device__ __forceinline__ uint32_t pack_h2(float a, float b) {
    uint32_t r;
    asm("cvt.rn.f16x2.f32 %0, %1, %2;" : "=r"(r) : "f"(b), "f"(a));
    return r;
}
__device__ __forceinline__ uint2 pack_h4(float4 v) {
    uint2 r;
    r.x = pack_h2(v.x, v.y);
    r.y = pack_h2(v.z, v.w);
    return r;
}

// ---------------- pack: X + QKV projection weights ----------------
__global__ void pack_xw(const float* __restrict__ x, const float* __restrict__ qw,
                        const float* __restrict__ kvw) {
    const int stride = gridDim.x * blockDim.x;
    const int tid = blockIdx.x * blockDim.x + threadIdx.x;

    const int NX4 = (T_SEQ * D_MODEL) >> 2;
    uint2* ahw = reinterpret_cast<uint2*>(g_Ah);
    const float4* x4 = reinterpret_cast<const float4*>(x);
    for (int i = tid; i < NX4; i += stride) ahw[i] = pack_h4(x4[i]);

    for (int d = blockIdx.x; d < D_MODEL; d += gridDim.x) {
        for (int c4 = threadIdx.x; c4 < (NPROJ >> 2); c4 += blockDim.x) {
            int col = c4 << 2;
            int h = col & 127;
            const float* srcp;
            if (col < 4096)      srcp = qw  + (((size_t)(col >> 7) * D_MODEL + d) << 7) + h;
            else if (col < 5120) srcp = kvw + (((size_t)((col - 4096) >> 7) * D_MODEL + d) << 7) + h;
            else                 srcp = kvw + (((size_t)(KVHEADS + ((col - 5120) >> 7)) * D_MODEL + d) << 7) + h;
            float4 v = *reinterpret_cast<const float4*>(srcp);
            *reinterpret_cast<uint2*>(&g_Bp[(size_t)d * NPROJ + col]) = pack_h4(v);
        }
    }
}

// ---------------- pack: out projection weights (side stream) ----------------
__global__ void pack_o(const float* __restrict__ ow) {
    const int stride = gridDim.x * blockDim.x;
    const int tid = blockIdx.x * blockDim.x + threadIdx.x;
    const int NO4 = (D_MODEL * D_MODEL) >> 2;
    uint2* bow = reinterpret_cast<uint2*>(g_Bo);
    const float4* ow4 = reinterpret_cast<const float4*>(ow);
    for (int i = tid; i < NO4; i += stride) bow[i] = pack_h4(ow4[i]);
}

// ---------------- fp16 single-plane GEMM: CTA 128x256, warp 64x64, 3-stage ----------------
#define SA2 72
#define SB2 264
#define A_PLANE (128 * SA2)
#define B_PLANE (64 * SB2)
#define OFF_B   A_PLANE
#define STAGE_E (A_PLANE + B_PLANE)

__global__ __launch_bounds__(256)
void gemm_fp16(const __half* __restrict__ Ahg, const __half* __restrict__ Bg,
               float* __restrict__ C, __half* __restrict__ Vout,
               int M, int Nc, int Kd) {
    extern __shared__ __half smem[];
    const int tid  = threadIdx.x;
    const int lane = tid & 31;
    const int wid  = tid >> 5;
    const int wm   = wid >> 2;
    const int wn   = wid & 3;
    const int row0 = blockIdx.y * 128;
    const int n0   = blockIdx.x * 256;
    const int lrow = lane & 15;
    const int lcol = (lane >> 4) << 3;

    float acc[4][8][4];
    #pragma unroll
    for (int mt = 0; mt < 4; mt++)
        #pragma unroll
        for (int nt = 0; nt < 8; nt++)
            #pragma unroll
            for (int r = 0; r < 4; r++) acc[mt][nt][r] = 0.f;

    const int KT = Kd >> 6;

    auto stage_copy = [&](int buf, int k0) {
        __half* s = smem + buf * STAGE_E;
        #pragma unroll
        for (int c = tid; c < 1024; c += 256) {
            int r = c >> 3, col = (c & 7) << 3;
            size_t g = (size_t)(row0 + r) * Kd + k0 + col;
            cp16(s + r * SA2 + col, Ahg + g);
        }
        #pragma unroll
        for (int c = tid; c < 2048; c += 256) {
            int r = c >> 5, col = (c & 31) << 3;
            size_t g = (size_t)(k0 + r) * Nc + n0 + col;
            cp16(s + OFF_B + r * SB2 + col, Bg + g);
        }
    };

    stage_copy(0, 0);  cp_commit();
    stage_copy(1, 64); cp_commit();

    int stage = 0;
    for (int kt = 0; kt < KT; kt++) {
        if (kt < KT - 1) asm volatile("cp.async.wait_group 1;\n");
        else             asm volatile("cp.async.wait_group 0;\n");
        __syncthreads();
        if (kt + 2 < KT) {
            int nb = stage + 2; if (nb >= 3) nb -= 3;
            stage_copy(nb, (kt + 2) << 6);
            cp_commit();
        }

        const __half* s  = smem + stage * STAGE_E;
        const __half* Ah = s;
        const __half* Bs = s + OFF_B;

        #pragma unroll
        for (int k16 = 0; k16 < 4; k16++) {
            const int kc = k16 << 4;
            uint32_t ah[4][4];
            #pragma unroll
            for (int mt = 0; mt < 4; mt++) {
                const __half* pa = Ah + (wm * 64 + mt * 16 + lrow) * SA2 + kc + lcol;
                ldsm4(ah[mt][0], ah[mt][1], ah[mt][2], ah[mt][3], pa);
            }
            #pragma unroll
            for (int jt = 0; jt < 4; jt++) {
                uint32_t bh[4];
                const __half* pb = Bs + (kc + lrow) * SB2 + wn * 64 + jt * 16 + lcol;
                ldsm4t(bh[0], bh[1], bh[2], bh[3], pb);
                #pragma unroll
                for (int mt = 0; mt < 4; mt++) {
                    mma16816(acc[mt][2 * jt],     ah[mt], bh[0], bh[1]);
                    mma16816(acc[mt][2 * jt + 1], ah[mt], bh[2], bh[3]);
                }
            }
        }
        stage++; if (stage == 3) stage = 0;
    }

    float* Cb = C + (size_t)(row0 + wm * 64) * Nc + n0 + wn * 64;
    const int g  = lane >> 2;
    const int tc = (lane & 3) * 2;
    #pragma unroll
    for (int mt = 0; mt < 4; mt++)
        #pragma unroll
        for (int nt = 0; nt < 8; nt++) {
            float2 v0 = make_float2(acc[mt][nt][0], acc[mt][nt][1]);
            float2 v1 = make_float2(acc[mt][nt][2], acc[mt][nt][3]);
            *reinterpret_cast<float2*>(Cb + (size_t)(mt * 16 + g) * Nc + nt * 8 + tc)     = v0;
            *reinterpret_cast<float2*>(Cb + (size_t)(mt * 16 + g + 8) * Nc + nt * 8 + tc) = v1;
            if (Vout) {
                int col = n0 + wn * 64 + nt * 8 + tc;
                if (col >= 5120) {
                    int vcol = col - 5120;
                    int r0v = row0 + wm * 64 + mt * 16 + g;
                    *reinterpret_cast<uint32_t*>(Vout + (size_t)r0v * 1024 + vcol)       = pack_h2(v0.x, v0.y);
                    *reinterpret_cast<uint32_t*>(Vout + (size_t)(r0v + 8) * 1024 + vcol) = pack_h2(v1.x, v1.y);
                }
            }
        }
}

// ---------------- fused RoPE + scale -> single fp16 plane ----------------
__global__ void rope_fp16(const float* __restrict__ src, int srcStride, int srcOff,
                          const int* __restrict__ pos, int n_heads, float scale,
                          __half* __restrict__ dh) {
    int idx = blockIdx.x * blockDim.x + threadIdx.x;
    int total = T_SEQ * n_heads * 64;
    if (idx >= total) return;
    int hh = idx & 63;
    int nh = (idx >> 6) % n_heads;
    int t  = idx / (n_heads << 6);
    float ts  = powf(10000.0f, (float)hh * (1.0f / 64.0f));
    float ang = (float)pos[t] / ts;
    float sv = sinf(ang), cv = cosf(ang);
    size_t sbase = (size_t)t * srcStride + srcOff + nh * HDIM;
    size_t dbase = (size_t)t * (n_heads * HDIM) + nh * HDIM;
    float a = src[sbase + hh], b = src[sbase + hh + 64];
    dh[dbase + hh]      = __float2half_rn((a * cv - b * sv) * scale);
    dh[dbase + hh + 64] = __float2half_rn((b * cv + a * sv) * scale);
}

// ---------------- fp16 tensor-core flash attention (Q in smem, 2 CTAs/SM) ----------------
#define AST 136
#define PLANE (64 * AST)
#define QPLANE (128 * AST)
#define STAGE2A (2 * PLANE)

__global__ __launch_bounds__(256, 2)
void attn_tc(const int* __restrict__ segpos) {
    extern __shared__ __half dsm[];
    __half* Qsm = dsm;
    __half* kvs = dsm + QPLANE;
    __shared__ int sp[128];
    __shared__ int s_pmin, s_pmax;

    const int n   = blockIdx.x;
    const int t0  = blockIdx.y * 128;
    const int kvh = n >> 2;
    const int tid = threadIdx.x;
    const int lane = tid & 31;
    const int w = tid >> 5;
    const int g8 = lane >> 2;
    const int q2 = (lane & 3) << 1;

    #pragma unroll
    for (int i = tid; i < 2048; i += 256) {
        int r = i >> 4, c = (i & 15) << 3;
        cp16(Qsm + r * AST + c, g_Qs + (size_t)(t0 + r) * (NHEADS * HDIM) + n * HDIM + c);
    }
    cp_commit();

    if (tid < 128) sp[tid] = segpos[t0 + tid];
    __syncthreads();
    if (tid == 0) {
        int mn = sp[0], mx = sp[0];
        for (int i = 1; i < 128; i++) { int v = sp[i]; mn = min(mn, v); mx = max(mx, v); }
        s_pmin = mn; s_pmax = mx;
    }
    __syncthreads();

    const int row0 = t0 + w * 16 + g8;

    float m[2]    = {-1e30f, -1e30f};
    float lsum[2] = {0.f, 0.f};
    float O[16][4];
    #pragma unroll
    for (int i = 0; i < 16; i++)
        #pragma unroll
        for (int j = 0; j < 4; j++) O[i][j] = 0.f;

    int s_lo = s_pmin - (WINDOW - 1); if (s_lo < 0) s_lo = 0;
    const int sb = s_lo & ~63;
    const int nIter = ((t0 + 127 - sb) >> 6) + 1;

    auto loadKV = [&](int stage, int s0) {
        __half* base = kvs + stage * STAGE2A;
        #pragma unroll
        for (int i = tid; i < 1024; i += 256) {
            int r = i >> 4, c = (i & 15) << 3;
            size_t g = (size_t)(s0 + r) * (KVHEADS * HDIM) + kvh * HDIM + c;
            cp16(base + r * AST + c,         g_Ks + g);
            cp16(base + PLANE + r * AST + c, g_Vs + g);
        }
    };

    loadKV(0, sb); cp_commit();
    if (nIter > 1) { loadKV(1, sb + 64); cp_commit(); }

    const int arow = lane & 15;
    const int asel = (lane & 16) ? 8 : 0;
    const int krow = (lane & 7) + ((lane & 16) ? 8 : 0);
    const int ksel = (lane & 8) ? 8 : 0;
    const int vkey = lane & 15;
    const int vsel = (lane & 16) ? 8 : 0;

    for (int it = 0; it < nIter; it++) {
        const int s0 = sb + (it << 6);
        if (it + 1 < nIter) asm volatile("cp.async.wait_group 1;\n");
        else                asm volatile("cp.async.wait_group 0;\n");
        __syncthreads();

        const __half* base = kvs + (it & 1) * STAGE2A;
        const __half* Ks = base;
        const __half* Vsm = base + PLANE;

        float S[8][4];
        #pragma unroll
        for (int i = 0; i < 8; i++)
            #pragma unroll
            for (int j = 0; j < 4; j++) S[i][j] = 0.f;

        #pragma unroll
        for (int k16 = 0; k16 < 8; k16++) {
            uint32_t qa[4];
            ldsm4(qa[0], qa[1], qa[2], qa[3],
                  Qsm + (w * 16 + arow) * AST + k16 * 16 + asel);
            uint32_t bh[4][4];
            #pragma unroll
            for (int nt = 0; nt < 4; nt++) {
                int koff = (nt * 16 + krow) * AST + k16 * 16 + ksel;
                ldsm4(bh[nt][0], bh[nt][1], bh[nt][2], bh[nt][3], Ks + koff);
            }
            #pragma unroll
            for (int nt = 0; nt < 4; nt++) {
                mma16816(S[2 * nt],     qa, bh[nt][0], bh[nt][1]);
                mma16816(S[2 * nt + 1], qa, bh[nt][2], bh[nt][3]);
            }
        }

        const bool interior = (s0 + 63 <= t0) && (s0 > s_pmax - WINDOW) && (s0 + 63 < s_pmin + WINDOW);
        if (interior) {
            #pragma unroll
            for (int nt = 0; nt < 8; nt++)
                #pragma unroll
                for (int jj = 0; jj < 4; jj++) {
                    float e = __expf(S[nt][jj] * 0.04f);
                    S[nt][jj] = 50.f - __fdividef(100.f, e + 1.f);
                }
        } else {
            const int sp_r0 = sp[w * 16 + g8];
            const int sp_r1 = sp[w * 16 + g8 + 8];
            #pragma unroll
            for (int nt = 0; nt < 8; nt++) {
                int scol0 = s0 + nt * 8 + q2;
                #pragma unroll
                for (int jj = 0; jj < 4; jj++) {
                    int s = scol0 + (jj & 1);
                    int t = row0 + ((jj & 2) ? 8 : 0);
                    int p = (jj & 2) ? sp_r1 : sp_r0;
                    float e = __expf(S[nt][jj] * 0.04f);
                    float c = 50.f - __fdividef(100.f, e + 1.f);
                    bool ok = (s <= t) && (s > p - WINDOW) && (s < p + WINDOW);
                    S[nt][jj] = ok ? c : -1e30f;
                }
            }
        }

        #pragma unroll
        for (int h = 0; h < 2; h++) {
            float mx = -1e30f;
            #pragma unroll
            for (int nt = 0; nt < 8; nt++)
                mx = fmaxf(mx, fmaxf(S[nt][2 * h], S[nt][2 * h + 1]));
            mx = fmaxf(mx, __shfl_xor_sync(0xffffffffu, mx, 1));
            mx = fmaxf(mx, __shfl_xor_sync(0xffffffffu, mx, 2));
            float mnew  = fmaxf(m[h], mx);
            float alpha = __expf(m[h] - mnew);
            float rs = 0.f;
            #pragma unroll
            for (int nt = 0; nt < 8; nt++) {
                #pragma unroll
                for (int e2 = 0; e2 < 2; e2++) {
                    float sv = S[nt][2 * h + e2];
                    float pv = (sv < -9e29f) ? 0.f : __expf(sv - mnew);
                    S[nt][2 * h + e2] = pv;
                    rs += pv;
                }
            }
            rs += __shfl_xor_sync(0xffffffffu, rs, 1);
            rs += __shfl_xor_sync(0xffffffffu, rs, 2);
            lsum[h] = lsum[h] * alpha + rs;
            #pragma unroll
            for (int nt = 0; nt < 16; nt++) {
                O[nt][2 * h]     *= alpha;
                O[nt][2 * h + 1] *= alpha;
            }
            m[h] = mnew;
        }

        #pragma unroll
        for (int kt = 0; kt < 4; kt++) {
            uint32_t pa[4];
            pa[0] = pack_h2(S[2 * kt][0],     S[2 * kt][1]);
            pa[1] = pack_h2(S[2 * kt][2],     S[2 * kt][3]);
            pa[2] = pack_h2(S[2 * kt + 1][0], S[2 * kt + 1][1]);
            pa[3] = pack_h2(S[2 * kt + 1][2], S[2 * kt + 1][3]);
            #pragma unroll
            for (int hp = 0; hp < 4; hp++) {
                uint32_t v0[4], v1[4];
                int vbase = (kt * 16 + vkey) * AST + (2 * hp) * 16 + vsel;
                ldsm4t(v0[0], v0[1], v0[2], v0[3], Vsm + vbase);
                ldsm4t(v1[0], v1[1], v1[2], v1[3], Vsm + vbase + 16);
                mma16816(O[4 * hp],     pa, v0[0], v0[1]);
                mma16816(O[4 * hp + 1], pa, v0[2], v0[3]);
                mma16816(O[4 * hp + 2], pa, v1[0], v1[1]);
                mma16816(O[4 * hp + 3], pa, v1[2], v1[3]);
            }
        }
        __syncthreads();
        if (it + 2 < nIter) { loadKV(it & 1, s0 + 128); cp_commit(); }
    }

    #pragma unroll
    for (int h = 0; h < 2; h++) {
        float inv = 1.0f / lsum[h];
        int row = row0 + 8 * h;
        size_t dbase = (size_t)row * D_MODEL + n * HDIM + q2;
        #pragma unroll
        for (int nt = 0; nt < 16; nt++) {
            *reinterpret_cast<uint32_t*>(g_Ah + dbase + nt * 8) =
                pack_h2(O[nt][2 * h] * inv, O[nt][2 * h + 1] * inv);
        }
    }
}

// ---------------- launch ----------------
extern "C" void kernel_launch(void* const* d_in, const int* in_sizes, int n_in,
                              void* d_out, int out_size) {
    const float* x      = (const float*)d_in[0];
    const int*   segpos = (const int*)d_in[1];
    const float* qw   = (const float*)d_in[3];
    const float* kvw  = (const float*)d_in[4];
    const float* outw = (const float*)d_in[5];
    float* out = (float*)d_out;

    __half *pAh, *pBp, *pBo, *pQs, *pKs, *pVs;
    float* pQKV;
    cudaGetSymbolAddress((void**)&pAh, g_Ah);
    cudaGetSymbolAddress((void**)&pBp, g_Bp);
    cudaGetSymbolAddress((void**)&pBo, g_Bo);
    cudaGetSymbolAddress((void**)&pQs, g_Qs);
    cudaGetSymbolAddress((void**)&pKs, g_Ks);
    cudaGetSymbolAddress((void**)&pVs, g_Vs);
    cudaGetSymbolAddress((void**)&pQKV, g_QKV);

    static cudaStream_t s2 = nullptr;
    static cudaEvent_t evFork = nullptr, evJoin = nullptr;
    if (!s2) {
        cudaStreamCreateWithFlags(&s2, cudaStreamNonBlocking);
        cudaEventCreateWithFlags(&evFork, cudaEventDisableTiming);
        cudaEventCreateWithFlags(&evJoin, cudaEventDisableTiming);
    }

    cudaEventRecord(evFork, 0);
    cudaStreamWaitEvent(s2, evFork, 0);
    pack_o<<<1024, 256, 0, s2>>>(outw);
    cudaEventRecord(evJoin, s2);

    pack_xw<<<2048, 256>>>(x, qw, kvw);

    const int GEMM_SMEM = 3 * STAGE_E * (int)sizeof(__half);
    cudaFuncSetAttribute(gemm_fp16, cudaFuncAttributeMaxDynamicSharedMemorySize, GEMM_SMEM);

    gemm_fp16<<<dim3(NPROJ / 256, T_SEQ / 128), 256, GEMM_SMEM>>>(
        pAh, pBp, pQKV, pVs, T_SEQ, NPROJ, D_MODEL);

    rope_fp16<<<(T_SEQ * NHEADS * 64 + 255) / 256, 256>>>(pQKV, NPROJ, 0, segpos, NHEADS,
                                                          0.08838834764831845f, pQs);
    rope_fp16<<<(T_SEQ * KVHEADS * 64 + 255) / 256, 256>>>(pQKV, NPROJ, 4096, segpos, KVHEADS,
                                                           1.0f, pKs);

    const int ATTN_SMEM = (QPLANE + 2 * STAGE2A) * (int)sizeof(__half);
    cudaFuncSetAttribute(attn_tc, cudaFuncAttributeMaxDynamicSharedMemorySize, ATTN_SMEM);
    attn_tc<<<dim3(NHEADS, T_SEQ / 128), 256, ATTN_SMEM>>>(segpos);

    cudaStreamWaitEvent(0, evJoin, 0);
    gemm_fp16<<<dim3(D_MODEL / 256, T_SEQ / 128), 256, GEMM_SMEM>>>(
        pAh, pBo, out, nullptr, T_SEQ, D_MODEL, D_MODEL);
}

// round 17
// speedup vs baseline: 1.0174x; 1.0174x over previous
#include <cuda_runtime.h>
#include <cuda_fp16.h>
#include <math.h>
#include <stdint.h>

#define T_SEQ   2048
#define D_MODEL 4096
#define NHEADS  32
#define KVHEADS 8
#define HDIM    128
#define WINDOW  1024
#define NPROJ   6144   // 4096 Q + 1024 K + 1024 V

// ---------------- scratch (device globals) ----------------
__device__ __half g_Ah[T_SEQ * D_MODEL];          // A plane: X, later Enc
__device__ __half g_Bp[D_MODEL * NPROJ];          // packed QKV proj weights (D, 6144)
__device__ __half g_Bo[D_MODEL * D_MODEL];        // out proj (N*H, D)
__device__ float  g_QKV[T_SEQ * NPROJ];
// attention operands (single fp16 planes)
__device__ __half g_Qs[T_SEQ * NHEADS * HDIM];
__device__ __half g_Ks[T_SEQ * KVHEADS * HDIM];
__device__ __half g_Vs[T_SEQ * KVHEADS * HDIM];

// ---------------- helpers ----------------
__device__ __forceinline__ void cp16(void* dst, const void* src) {
    uint32_t d = (uint32_t)__cvta_generic_to_shared(dst);
    asm volatile("cp.async.cg.shared.global [%0], [%1], 16;\n" :: "r"(d), "l"(src));
}
__device__ __forceinline__ void cp_commit() { asm volatile("cp.async.commit_group;\n"); }

__device__ __forceinline__ void ldsm4(uint32_t& r0, uint32_t& r1, uint32_t& r2, uint32_t& r3,
                                      const __half* p) {
    uint32_t a = (uint32_t)__cvta_generic_to_shared(p);
    asm volatile("ldmatrix.sync.aligned.m8n8.x4.shared.b16 {%0,%1,%2,%3}, [%4];"
                 : "=r"(r0), "=r"(r1), "=r"(r2), "=r"(r3) : "r"(a));
}
__device__ __forceinline__ void ldsm4t(uint32_t& r0, uint32_t& r1, uint32_t& r2, uint32_t& r3,
                                       const __half* p) {
    uint32_t a = (uint32_t)__cvta_generic_to_shared(p);
    asm volatile("ldmatrix.sync.aligned.m8n8.x4.trans.shared.b16 {%0,%1,%2,%3}, [%4];"
                 : "=r"(r0), "=r"(r1), "=r"(r2), "=r"(r3) : "r"(a));
}
__device__ __forceinline__ void mma16816(float* c, const uint32_t* a, uint32_t b0, uint32_t b1) {
    asm volatile(
        "mma.sync.aligned.m16n8k16.row.col.f32.f16.f16.f32 "
        "{%0,%1,%2,%3}, {%4,%5,%6,%7}, {%8,%9}, {%0,%1,%2,%3};"
        : "+f"(c[0]), "+f"(c[1]), "+f"(c[2]), "+f"(c[3])
        : "r"(a[0]), "r"(a[1]), "r"(a[2]), "r"(a[3]), "r"(b0), "r"(b1));
}
__device__ __forceinline__ uint32_t pack_h2(float a, float b) {
    uint32_t r;
    asm("cvt.rn.f16x2.f32 %0, %1, %2;" : "=r"(r) : "f"(b), "f"(a));
    return r;
}
__device__ __forceinline__ uint2 pack_h4(float4 v) {
    uint2 r;
    r.x = pack_h2(v.x, v.y);
    r.y = pack_h2(v.z, v.w);
    return r;
}

// ---------------- pack: X + QKV projection weights ----------------
__global__ void pack_xw(const float* __restrict__ x, const float* __restrict__ qw,
                        const float* __restrict__ kvw) {
    const int stride = gridDim.x * blockDim.x;
    const int tid = blockIdx.x * blockDim.x + threadIdx.x;

    const int NX4 = (T_SEQ * D_MODEL) >> 2;
    uint2* ahw = reinterpret_cast<uint2*>(g_Ah);
    const float4* x4 = reinterpret_cast<const float4*>(x);
    for (int i = tid; i < NX4; i += stride) ahw[i] = pack_h4(x4[i]);

    for (int d = blockIdx.x; d < D_MODEL; d += gridDim.x) {
        for (int c4 = threadIdx.x; c4 < (NPROJ >> 2); c4 += blockDim.x) {
            int col = c4 << 2;
            int h = col & 127;
            const float* srcp;
            if (col < 4096)      srcp = qw  + (((size_t)(col >> 7) * D_MODEL + d) << 7) + h;
            else if (col < 5120) srcp = kvw + (((size_t)((col - 4096) >> 7) * D_MODEL + d) << 7) + h;
            else                 srcp = kvw + (((size_t)(KVHEADS + ((col - 5120) >> 7)) * D_MODEL + d) << 7) + h;
            float4 v = *reinterpret_cast<const float4*>(srcp);
            *reinterpret_cast<uint2*>(&g_Bp[(size_t)d * NPROJ + col]) = pack_h4(v);
        }
    }
}

// ---------------- pack: out projection weights (side stream) ----------------
__global__ void pack_o(const float* __restrict__ ow) {
    const int stride = gridDim.x * blockDim.x;
    const int tid = blockIdx.x * blockDim.x + threadIdx.x;
    const int NO4 = (D_MODEL * D_MODEL) >> 2;
    uint2* bow = reinterpret_cast<uint2*>(g_Bo);
    const float4* ow4 = reinterpret_cast<const float4*>(ow);
    for (int i = tid; i < NO4; i += stride) bow[i] = pack_h4(ow4[i]);
}

// ---------------- fp16 single-plane GEMM: CTA 128x256, warp 64x64, 3-stage ----------------
#define SA2 72
#define SB2 264
#define A_PLANE (128 * SA2)
#define B_PLANE (64 * SB2)
#define OFF_B   A_PLANE
#define STAGE_E (A_PLANE + B_PLANE)

__global__ __launch_bounds__(256)
void gemm_fp16(const __half* __restrict__ Ahg, const __half* __restrict__ Bg,
               float* __restrict__ C, __half* __restrict__ Vout,
               int M, int Nc, int Kd) {
    extern __shared__ __half smem[];
    const int tid  = threadIdx.x;
    const int lane = tid & 31;
    const int wid  = tid >> 5;
    const int wm   = wid >> 2;
    const int wn   = wid & 3;
    const int row0 = blockIdx.y * 128;
    const int n0   = blockIdx.x * 256;
    const int lrow = lane & 15;
    const int lcol = (lane >> 4) << 3;

    float acc[4][8][4];
    #pragma unroll
    for (int mt = 0; mt < 4; mt++)
        #pragma unroll
        for (int nt = 0; nt < 8; nt++)
            #pragma unroll
            for (int r = 0; r < 4; r++) acc[mt][nt][r] = 0.f;

    const int KT = Kd >> 6;

    auto stage_copy = [&](int buf, int k0) {
        __half* s = smem + buf * STAGE_E;
        #pragma unroll
        for (int c = tid; c < 1024; c += 256) {
            int r = c >> 3, col = (c & 7) << 3;
            size_t g = (size_t)(row0 + r) * Kd + k0 + col;
            cp16(s + r * SA2 + col, Ahg + g);
        }
        #pragma unroll
        for (int c = tid; c < 2048; c += 256) {
            int r = c >> 5, col = (c & 31) << 3;
            size_t g = (size_t)(k0 + r) * Nc + n0 + col;
            cp16(s + OFF_B + r * SB2 + col, Bg + g);
        }
    };

    stage_copy(0, 0);  cp_commit();
    stage_copy(1, 64); cp_commit();

    int stage = 0;
    for (int kt = 0; kt < KT; kt++) {
        if (kt < KT - 1) asm volatile("cp.async.wait_group 1;\n");
        else             asm volatile("cp.async.wait_group 0;\n");
        __syncthreads();
        if (kt + 2 < KT) {
            int nb = stage + 2; if (nb >= 3) nb -= 3;
            stage_copy(nb, (kt + 2) << 6);
            cp_commit();
        }

        const __half* s  = smem + stage * STAGE_E;
        const __half* Ah = s;
        const __half* Bs = s + OFF_B;

        #pragma unroll
        for (int k16 = 0; k16 < 4; k16++) {
            const int kc = k16 << 4;
            uint32_t ah[4][4];
            #pragma unroll
            for (int mt = 0; mt < 4; mt++) {
                const __half* pa = Ah + (wm * 64 + mt * 16 + lrow) * SA2 + kc + lcol;
                ldsm4(ah[mt][0], ah[mt][1], ah[mt][2], ah[mt][3], pa);
            }
            #pragma unroll
            for (int jt = 0; jt < 4; jt++) {
                uint32_t bh[4];
                const __half* pb = Bs + (kc + lrow) * SB2 + wn * 64 + jt * 16 + lcol;
                ldsm4t(bh[0], bh[1], bh[2], bh[3], pb);
                #pragma unroll
                for (int mt = 0; mt < 4; mt++) {
                    mma16816(acc[mt][2 * jt],     ah[mt], bh[0], bh[1]);
                    mma16816(acc[mt][2 * jt + 1], ah[mt], bh[2], bh[3]);
                }
            }
        }
        stage++; if (stage == 3) stage = 0;
    }

    float* Cb = C + (size_t)(row0 + wm * 64) * Nc + n0 + wn * 64;
    const int g  = lane >> 2;
    const int tc = (lane & 3) * 2;
    #pragma unroll
    for (int mt = 0; mt < 4; mt++)
        #pragma unroll
        for (int nt = 0; nt < 8; nt++) {
            float2 v0 = make_float2(acc[mt][nt][0], acc[mt][nt][1]);
            float2 v1 = make_float2(acc[mt][nt][2], acc[mt][nt][3]);
            *reinterpret_cast<float2*>(Cb + (size_t)(mt * 16 + g) * Nc + nt * 8 + tc)     = v0;
            *reinterpret_cast<float2*>(Cb + (size_t)(mt * 16 + g + 8) * Nc + nt * 8 + tc) = v1;
            if (Vout) {
                int col = n0 + wn * 64 + nt * 8 + tc;
                if (col >= 5120) {
                    int vcol = col - 5120;
                    int r0v = row0 + wm * 64 + mt * 16 + g;
                    *reinterpret_cast<uint32_t*>(Vout + (size_t)r0v * 1024 + vcol)       = pack_h2(v0.x, v0.y);
                    *reinterpret_cast<uint32_t*>(Vout + (size_t)(r0v + 8) * 1024 + vcol) = pack_h2(v1.x, v1.y);
                }
            }
        }
}

// ---------------- fused RoPE (Q and K in one launch) -> fp16 planes ----------------
#define NQ_ROPE (T_SEQ * NHEADS * 64)
#define NK_ROPE (T_SEQ * KVHEADS * 64)

__global__ void rope_all(const float* __restrict__ src, const int* __restrict__ pos,
                         __half* __restrict__ dq, __half* __restrict__ dk) {
    int idx = blockIdx.x * blockDim.x + threadIdx.x;
    int n_heads, srcOff;
    float scale;
    __half* dh;
    if (idx < NQ_ROPE) {
        n_heads = NHEADS; srcOff = 0; scale = 0.08838834764831845f; dh = dq;
    } else {
        idx -= NQ_ROPE;
        if (idx >= NK_ROPE) return;
        n_heads = KVHEADS; srcOff = 4096; scale = 1.0f; dh = dk;
    }
    int hh = idx & 63;
    int nh = (idx >> 6) % n_heads;
    int t  = idx / (n_heads << 6);
    float ts  = powf(10000.0f, (float)hh * (1.0f / 64.0f));
    float ang = (float)pos[t] / ts;
    float sv = sinf(ang), cv = cosf(ang);
    size_t sbase = (size_t)t * NPROJ + srcOff + nh * HDIM;
    size_t dbase = (size_t)t * (n_heads * HDIM) + nh * HDIM;
    float a = src[sbase + hh], b = src[sbase + hh + 64];
    dh[dbase + hh]      = __float2half_rn((a * cv - b * sv) * scale);
    dh[dbase + hh + 64] = __float2half_rn((b * cv + a * sv) * scale);
}

// ---------------- fp16 tensor-core flash attention (Q in smem, 2 CTAs/SM) ----------------
#define AST 136
#define PLANE (64 * AST)
#define QPLANE (128 * AST)
#define STAGE2A (2 * PLANE)

__global__ __launch_bounds__(256, 2)
void attn_tc(const int* __restrict__ segpos) {
    extern __shared__ __half dsm[];
    __half* Qsm = dsm;
    __half* kvs = dsm + QPLANE;
    __shared__ int sp[128];
    __shared__ int s_pmin, s_pmax;

    const int n   = blockIdx.x;
    // longest-first: largest t0 (most iterations) scheduled earliest
    const int t0  = (gridDim.y - 1 - blockIdx.y) * 128;
    const int kvh = n >> 2;
    const int tid = threadIdx.x;
    const int lane = tid & 31;
    const int w = tid >> 5;
    const int g8 = lane >> 2;
    const int q2 = (lane & 3) << 1;

    #pragma unroll
    for (int i = tid; i < 2048; i += 256) {
        int r = i >> 4, c = (i & 15) << 3;
        cp16(Qsm + r * AST + c, g_Qs + (size_t)(t0 + r) * (NHEADS * HDIM) + n * HDIM + c);
    }
    cp_commit();

    if (tid < 128) sp[tid] = segpos[t0 + tid];
    __syncthreads();
    if (tid == 0) {
        int mn = sp[0], mx = sp[0];
        for (int i = 1; i < 128; i++) { int v = sp[i]; mn = min(mn, v); mx = max(mx, v); }
        s_pmin = mn; s_pmax = mx;
    }
    __syncthreads();

    const int row0 = t0 + w * 16 + g8;

    float m[2]    = {-1e30f, -1e30f};
    float lsum[2] = {0.f, 0.f};
    float O[16][4];
    #pragma unroll
    for (int i = 0; i < 16; i++)
        #pragma unroll
        for (int j = 0; j < 4; j++) O[i][j] = 0.f;

    int s_lo = s_pmin - (WINDOW - 1); if (s_lo < 0) s_lo = 0;
    const int sb = s_lo & ~63;
    const int nIter = ((t0 + 127 - sb) >> 6) + 1;

    auto loadKV = [&](int stage, int s0) {
        __half* base = kvs + stage * STAGE2A;
        #pragma unroll
        for (int i = tid; i < 1024; i += 256) {
            int r = i >> 4, c = (i & 15) << 3;
            size_t g = (size_t)(s0 + r) * (KVHEADS * HDIM) + kvh * HDIM + c;
            cp16(base + r * AST + c,         g_Ks + g);
            cp16(base + PLANE + r * AST + c, g_Vs + g);
        }
    };

    loadKV(0, sb); cp_commit();
    if (nIter > 1) { loadKV(1, sb + 64); cp_commit(); }

    const int arow = lane & 15;
    const int asel = (lane & 16) ? 8 : 0;
    const int krow = (lane & 7) + ((lane & 16) ? 8 : 0);
    const int ksel = (lane & 8) ? 8 : 0;
    const int vkey = lane & 15;
    const int vsel = (lane & 16) ? 8 : 0;

    for (int it = 0; it < nIter; it++) {
        const int s0 = sb + (it << 6);
        if (it + 1 < nIter) asm volatile("cp.async.wait_group 1;\n");
        else                asm volatile("cp.async.wait_group 0;\n");
        __syncthreads();

        const __half* base = kvs + (it & 1) * STAGE2A;
        const __half* Ks = base;
        const __half* Vsm = base + PLANE;

        float S[8][4];
        #pragma unroll
        for (int i = 0; i < 8; i++)
            #pragma unroll
            for (int j = 0; j < 4; j++) S[i][j] = 0.f;

        #pragma unroll
        for (int k16 = 0; k16 < 8; k16++) {
            uint32_t qa[4];
            ldsm4(qa[0], qa[1], qa[2], qa[3],
                  Qsm + (w * 16 + arow) * AST + k16 * 16 + asel);
            uint32_t bh[4][4];
            #pragma unroll
            for (int nt = 0; nt < 4; nt++) {
                int koff = (nt * 16 + krow) * AST + k16 * 16 + ksel;
                ldsm4(bh[nt][0], bh[nt][1], bh[nt][2], bh[nt][3], Ks + koff);
            }
            #pragma unroll
            for (int nt = 0; nt < 4; nt++) {
                mma16816(S[2 * nt],     qa, bh[nt][0], bh[nt][1]);
                mma16816(S[2 * nt + 1], qa, bh[nt][2], bh[nt][3]);
            }
        }

        const bool interior = (s0 + 63 <= t0) && (s0 > s_pmax - WINDOW) && (s0 + 63 < s_pmin + WINDOW);
        if (interior) {
            #pragma unroll
            for (int nt = 0; nt < 8; nt++)
                #pragma unroll
                for (int jj = 0; jj < 4; jj++) {
                    float e = __expf(S[nt][jj] * 0.04f);
                    S[nt][jj] = 50.f - __fdividef(100.f, e + 1.f);
                }
        } else {
            const int sp_r0 = sp[w * 16 + g8];
            const int sp_r1 = sp[w * 16 + g8 + 8];
            #pragma unroll
            for (int nt = 0; nt < 8; nt++) {
                int scol0 = s0 + nt * 8 + q2;
                #pragma unroll
                for (int jj = 0; jj < 4; jj++) {
                    int s = scol0 + (jj & 1);
                    int t = row0 + ((jj & 2) ? 8 : 0);
                    int p = (jj & 2) ? sp_r1 : sp_r0;
                    float e = __expf(S[nt][jj] * 0.04f);
                    float c = 50.f - __fdividef(100.f, e + 1.f);
                    bool ok = (s <= t) && (s > p - WINDOW) && (s < p + WINDOW);
                    S[nt][jj] = ok ? c : -1e30f;
                }
            }
        }

        #pragma unroll
        for (int h = 0; h < 2; h++) {
            float mx = -1e30f;
            #pragma unroll
            for (int nt = 0; nt < 8; nt++)
                mx = fmaxf(mx, fmaxf(S[nt][2 * h], S[nt][2 * h + 1]));
            mx = fmaxf(mx, __shfl_xor_sync(0xffffffffu, mx, 1));
            mx = fmaxf(mx, __shfl_xor_sync(0xffffffffu, mx, 2));
            float mnew  = fmaxf(m[h], mx);
            float alpha = __expf(m[h] - mnew);
            float rs = 0.f;
            #pragma unroll
            for (int nt = 0; nt < 8; nt++) {
                #pragma unroll
                for (int e2 = 0; e2 < 2; e2++) {
                    float sv = S[nt][2 * h + e2];
                    float pv = (sv < -9e29f) ? 0.f : __expf(sv - mnew);
                    S[nt][2 * h + e2] = pv;
                    rs += pv;
                }
            }
            rs += __shfl_xor_sync(0xffffffffu, rs, 1);
            rs += __shfl_xor_sync(0xffffffffu, rs, 2);
            lsum[h] = lsum[h] * alpha + rs;
            #pragma unroll
            for (int nt = 0; nt < 16; nt++) {
                O[nt][2 * h]     *= alpha;
                O[nt][2 * h + 1] *= alpha;
            }
            m[h] = mnew;
        }

        #pragma unroll
        for (int kt = 0; kt < 4; kt++) {
            uint32_t pa[4];
            pa[0] = pack_h2(S[2 * kt][0],     S[2 * kt][1]);
            pa[1] = pack_h2(S[2 * kt][2],     S[2 * kt][3]);
            pa[2] = pack_h2(S[2 * kt + 1][0], S[2 * kt + 1][1]);
            pa[3] = pack_h2(S[2 * kt + 1][2], S[2 * kt + 1][3]);
            #pragma unroll
            for (int hp = 0; hp < 4; hp++) {
                uint32_t v0[4], v1[4];
                int vbase = (kt * 16 + vkey) * AST + (2 * hp) * 16 + vsel;
                ldsm4t(v0[0], v0[1], v0[2], v0[3], Vsm + vbase);
                ldsm4t(v1[0], v1[1], v1[2], v1[3], Vsm + vbase + 16);
                mma16816(O[4 * hp],     pa, v0[0], v0[1]);
                mma16816(O[4 * hp + 1], pa, v0[2], v0[3]);
                mma16816(O[4 * hp + 2], pa, v1[0], v1[1]);
                mma16816(O[4 * hp + 3], pa, v1[2], v1[3]);
            }
        }
        __syncthreads();
        if (it + 2 < nIter) { loadKV(it & 1, s0 + 128); cp_commit(); }
    }

    #pragma unroll
    for (int h = 0; h < 2; h++) {
        float inv = 1.0f / lsum[h];
        int row = row0 + 8 * h;
        size_t dbase = (size_t)row * D_MODEL + n * HDIM + q2;
        #pragma unroll
        for (int nt = 0; nt < 16; nt++) {
            *reinterpret_cast<uint32_t*>(g_Ah + dbase + nt * 8) =
                pack_h2(O[nt][2 * h] * inv, O[nt][2 * h + 1] * inv);
        }
    }
}

// ---------------- launch ----------------
extern "C" void kernel_launch(void* const* d_in, const int* in_sizes, int n_in,
                              void* d_out, int out_size) {
    const float* x      = (const float*)d_in[0];
    const int*   segpos = (const int*)d_in[1];
    const float* qw   = (const float*)d_in[3];
    const float* kvw  = (const float*)d_in[4];
    const float* outw = (const float*)d_in[5];
    float* out = (float*)d_out;

    __half *pAh, *pBp, *pBo, *pQs, *pKs, *pVs;
    float* pQKV;
    cudaGetSymbolAddress((void**)&pAh, g_Ah);
    cudaGetSymbolAddress((void**)&pBp, g_Bp);
    cudaGetSymbolAddress((void**)&pBo, g_Bo);
    cudaGetSymbolAddress((void**)&pQs, g_Qs);
    cudaGetSymbolAddress((void**)&pKs, g_Ks);
    cudaGetSymbolAddress((void**)&pVs, g_Vs);
    cudaGetSymbolAddress((void**)&pQKV, g_QKV);

    static cudaStream_t s2 = nullptr;
    static cudaEvent_t evFork = nullptr, evJoin = nullptr;
    if (!s2) {
        cudaStreamCreateWithFlags(&s2, cudaStreamNonBlocking);
        cudaEventCreateWithFlags(&evFork, cudaEventDisableTiming);
        cudaEventCreateWithFlags(&evJoin, cudaEventDisableTiming);
    }

    cudaEventRecord(evFork, 0);
    cudaStreamWaitEvent(s2, evFork, 0);
    pack_o<<<1024, 256, 0, s2>>>(outw);
    cudaEventRecord(evJoin, s2);

    pack_xw<<<2048, 256>>>(x, qw, kvw);

    const int GEMM_SMEM = 3 * STAGE_E * (int)sizeof(__half);
    cudaFuncSetAttribute(gemm_fp16, cudaFuncAttributeMaxDynamicSharedMemorySize, GEMM_SMEM);

    gemm_fp16<<<dim3(NPROJ / 256, T_SEQ / 128), 256, GEMM_SMEM>>>(
        pAh, pBp, pQKV, pVs, T_SEQ, NPROJ, D_MODEL);

    rope_all<<<(NQ_ROPE + NK_ROPE + 255) / 256, 256>>>(pQKV, segpos, pQs, pKs);

    const int ATTN_SMEM = (QPLANE + 2 * STAGE2A) * (int)sizeof(__half);
    cudaFuncSetAttribute(attn_tc, cudaFuncAttributeMaxDynamicSharedMemorySize, ATTN_SMEM);
    attn_tc<<<dim3(NHEADS, T_SEQ / 128), 256, ATTN_SMEM>>>(segpos);

    cudaStreamWaitEvent(0, evJoin, 0);
    gemm_fp16<<<dim3(D_MODEL / 256, T_SEQ / 128), 256, GEMM_SMEM>>>(
        pAh, pBo, out, nullptr, T_SEQ, D_MODEL, D_MODEL);
}